// round 15
// baseline (speedup 1.0000x reference)
#include <cuda_runtime.h>
#include <cuda_fp16.h>
#include <cstddef>
#include <cstdint>

// Problem constants
#define BB   2048
#define TT   512
#define D_IN 4
#define HH   64
#define LL   4
#define OUTN 5
#define G4   256   // 4*H

// -------------------------- device scratch --------------------------------
__device__ __half g_hsA[(size_t)TT * BB * HH];    // 128 MB ping (half)
__device__ __half g_hsB[(size_t)TT * BB * HH];    // 128 MB pong (half)
__device__ float  g_bias[LL][G4];

__device__ __forceinline__ float sigf(float x) {
    return __fdividef(1.0f, 1.0f + __expf(-x));
}
__device__ __forceinline__ float tanhg(float x) {
    return __fdividef(2.0f, 1.0f + __expf(-2.0f * x)) - 1.0f;
}

union H2U { __half2 h; uint32_t u; };
__device__ __forceinline__ uint32_t pack_h2(float a, float b) {
    H2U v; v.h = __floats2half2_rn(a, b); return v.u;
}

// fp16 MMA, f32 accumulate: A row-major 16x16, B col-major 16x8.
#define MMA_F16(c, a0, a1, a2, a3, b) \
    asm volatile("mma.sync.aligned.m16n8k16.row.col.f32.f16.f16.f32 " \
        "{%0,%1,%2,%3}, {%4,%5,%6,%7}, {%8,%9}, {%0,%1,%2,%3};" \
        : "+f"((c)[0]), "+f"((c)[1]), "+f"((c)[2]), "+f"((c)[3]) \
        : "r"(a0), "r"(a1), "r"(a2), "r"(a3), \
          "r"((b)[0]), "r"((b)[1]))

// h tile: 8 rows x 64 halfs, row stride 72 halfs (36 words; bank = 4lr+lc).
#define ASTRH 72
#define AST2  36

// ---------------------------------------------------------------------------
__global__ void prep_kernel(const float* __restrict__ b_ih,
                            const float* __restrict__ b_hh) {
    int idx = blockIdx.x * blockDim.x + threadIdx.x;
    if (idx >= LL * G4) return;
    g_bias[idx >> 8][idx & 255] = b_ih[idx] + b_hh[idx];
}

// ====================== fused fp16 recurrence, 8-row tiles =================
// Grid BB/8 = 256 CTAs -> 2 CTAs/SM (launch_bounds caps regs at 128).
// A rows 8-15 are implicit zeros (a1 = a3 = 0 fragments); epilogue 1 row/thr.
// x fragments prefetched straight from GMEM into registers (no Ax SMEM).
template <bool L0>
__global__ void __launch_bounds__(256, 2)
lstm_rec_f16(const float* __restrict__ xin, const __half* __restrict__ hs_prev,
             const float* __restrict__ Wih, const float* __restrict__ Whh,
             const float* __restrict__ bias, __half* __restrict__ ouths,
             int write_all) {
    __shared__ __half Ah[2][8 * ASTRH];

    const int tid  = threadIdx.x;
    const int wid  = tid >> 5;
    const int lane = tid & 31;
    const int lr   = lane >> 2;
    const int lc   = lane & 3;
    const int rowbase = blockIdx.x * 8;
    constexpr int XKC = L0 ? 1 : 4;

    // ---- weight fragments -> registers ----
    uint32_t bfh[4][4][2];
    uint32_t bfi[4][XKC][2];
    {
        int n = wid * 8 + lr;
        #pragma unroll
        for (int q = 0; q < 4; ++q) {
            int g = q * 64 + n;
            #pragma unroll
            for (int kc = 0; kc < 4; ++kc) {
                int kb = kc * 16;
                bfh[q][kc][0] = pack_h2(Whh[g * HH + kb + 2 * lc],
                                        Whh[g * HH + kb + 2 * lc + 1]);
                bfh[q][kc][1] = pack_h2(Whh[g * HH + kb + 2 * lc + 8],
                                        Whh[g * HH + kb + 2 * lc + 9]);
            }
            if (L0) {
                uint32_t b0 = 0;
                if (lc < 2)
                    b0 = pack_h2(Wih[g * D_IN + 2 * lc],
                                 Wih[g * D_IN + 2 * lc + 1]);
                bfi[q][0][0] = b0;
                bfi[q][0][1] = 0;
            } else {
                #pragma unroll
                for (int kc = 0; kc < 4; ++kc) {
                    int kb = kc * 16;
                    bfi[q][kc][0] = pack_h2(Wih[g * HH + kb + 2 * lc],
                                            Wih[g * HH + kb + 2 * lc + 1]);
                    bfi[q][kc][1] = pack_h2(Wih[g * HH + kb + 2 * lc + 8],
                                            Wih[g * HH + kb + 2 * lc + 9]);
                }
            }
        }
    }

    const int u0 = wid * 8 + 2 * lc;
    float2 bias_r[4];
    #pragma unroll
    for (int q = 0; q < 4; ++q)
        bias_r[q] = *(const float2*)&bias[q * 64 + u0];

    // ---- init h = 0 ----
    for (int i = tid; i < 8 * ASTRH; i += 256) {
        Ah[0][i] = __float2half(0.f);
        Ah[1][i] = __float2half(0.f);
    }
    __syncthreads();

    // ---- x fragment prefetch state (registers, MMA layout) ----
    // xf[kc][0] = A[lr][kc*16+2lc ..+1], xf[kc][1] = A[lr][kc*16+2lc+8 ..+9]
    uint32_t xf[XKC][2];
    const size_t xrow_off = (size_t)(rowbase + lr);
    if (L0) {
        uint32_t v = 0;
        if (lc < 2) {
            float2 p = *(const float2*)&xin[(xrow_off * TT + 0) * D_IN + 2 * lc];
            v = pack_h2(p.x, p.y);
        }
        xf[0][0] = v;
        xf[0][1] = 0;
    } else {
        #pragma unroll
        for (int kc = 0; kc < 4; ++kc) {
            const uint32_t* src = (const uint32_t*)
                &hs_prev[xrow_off * HH + kc * 16 + 2 * lc];
            xf[kc][0] = src[0];
            xf[kc][1] = src[4];   // +8 halfs
        }
    }

    float cst[2] = {0.f, 0.f};
    uint32_t* outu = (uint32_t*)ouths;

    for (int t = 0; t < TT; ++t) {
        const __half* Ahr = Ah[t & 1];
        __half*       Ahw = Ah[(t + 1) & 1];

        // ---- prefetch x(t+1) fragments (LDG hidden under this step) ----
        uint32_t xn[XKC][2];
        if (t + 1 < TT) {
            if (L0) {
                uint32_t v = 0;
                if (lc < 2) {
                    float2 p = *(const float2*)
                        &xin[(xrow_off * TT + t + 1) * D_IN + 2 * lc];
                    v = pack_h2(p.x, p.y);
                }
                xn[0][0] = v;
                xn[0][1] = 0;
            } else {
                #pragma unroll
                for (int kc = 0; kc < 4; ++kc) {
                    const uint32_t* src = (const uint32_t*)
                        &hs_prev[((size_t)(t + 1) * BB + rowbase + lr) * HH +
                                 kc * 16 + 2 * lc];
                    xn[kc][0] = src[0];
                    xn[kc][1] = src[4];
                }
            }
        }

        // ---- MMA: acc[q] = bias + x.W_ih^T + h.W_hh^T (rows 8-15 = 0) ----
        float acc[4][4];
        #pragma unroll
        for (int q = 0; q < 4; ++q) {
            acc[q][0] = bias_r[q].x; acc[q][1] = bias_r[q].y;
            acc[q][2] = 0.f;         acc[q][3] = 0.f;
        }

        #pragma unroll
        for (int kc = 0; kc < XKC; ++kc) {
            MMA_F16(acc[0], xf[kc][0], 0u, xf[kc][1], 0u, bfi[0][kc]);
            MMA_F16(acc[1], xf[kc][0], 0u, xf[kc][1], 0u, bfi[1][kc]);
            MMA_F16(acc[2], xf[kc][0], 0u, xf[kc][1], 0u, bfi[2][kc]);
            MMA_F16(acc[3], xf[kc][0], 0u, xf[kc][1], 0u, bfi[3][kc]);
        }
        #pragma unroll
        for (int kc = 0; kc < 4; ++kc) {
            int k = kc * 16 + 2 * lc;
            uint32_t a0 = *(const uint32_t*)&Ahr[lr * ASTRH + k];
            uint32_t a2 = *(const uint32_t*)&Ahr[lr * ASTRH + k + 8];
            MMA_F16(acc[0], a0, 0u, a2, 0u, bfh[0][kc]);
            MMA_F16(acc[1], a0, 0u, a2, 0u, bfh[1][kc]);
            MMA_F16(acc[2], a0, 0u, a2, 0u, bfh[2][kc]);
            MMA_F16(acc[3], a0, 0u, a2, 0u, bfh[3][kc]);
        }

        // ---- rotate x fragments ----
        #pragma unroll
        for (int kc = 0; kc < XKC; ++kc) {
            xf[kc][0] = xn[kc][0];
            xf[kc][1] = xn[kc][1];
        }

        // ---- epilogue: 1 row x 2 units, thread-local ----
        {
            float gi0 = sigf(acc[0][0]);
            float gf0 = sigf(acc[1][0]);
            float gg0 = tanhg(acc[2][0]);
            float go0 = sigf(acc[3][0]);
            float gi1 = sigf(acc[0][1]);
            float gf1 = sigf(acc[1][1]);
            float gg1 = tanhg(acc[2][1]);
            float go1 = sigf(acc[3][1]);

            float cn0 = gf0 * cst[0] + gi0 * gg0;
            float cn1 = gf1 * cst[1] + gi1 * gg1;
            cst[0] = cn0;
            cst[1] = cn1;
            float hn0 = go0 * tanhg(cn0);
            float hn1 = go1 * tanhg(cn1);

            uint32_t hpk = pack_h2(hn0, hn1);
            *(uint32_t*)&Ahw[lr * ASTRH + u0] = hpk;

            if (write_all || t == TT - 1) {
                size_t trow = (size_t)t * BB + rowbase + lr;
                outu[trow * 32 + 4 * wid + lc] = hpk;
            }
        }
        __syncthreads();   // h(t+1) visible for next step
    }
}

// ---------------------------------------------------------------------------
__global__ void fc_kernel(const __half* __restrict__ hs,
                          const float* __restrict__ Wfc,
                          const float* __restrict__ bfc,
                          float* __restrict__ out) {
    int idx = blockIdx.x * blockDim.x + threadIdx.x;
    if (idx >= BB * OUTN) return;
    int b = idx / OUTN, o = idx - b * OUTN;
    const __half* h = &hs[(size_t)(TT - 1) * (BB * HH) + (size_t)b * HH];
    float s = bfc[o];
    #pragma unroll
    for (int j = 0; j < HH; j++)
        s = fmaf(__half2float(h[j]), Wfc[o * HH + j], s);
    out[idx] = s;
}

// ---------------------------------------------------------------------------
extern "C" void kernel_launch(void* const* d_in, const int* in_sizes, int n_in,
                              void* d_out, int out_size) {
    const float* x     = (const float*)d_in[0];
    const float* W_ih0 = (const float*)d_in[1];
    const float* W_ihr = (const float*)d_in[2];
    const float* W_hh  = (const float*)d_in[3];
    const float* b_ih  = (const float*)d_in[4];
    const float* b_hh  = (const float*)d_in[5];
    const float* W_fc  = (const float*)d_in[6];
    const float* b_fc  = (const float*)d_in[7];
    float* out = (float*)d_out;

    __half *hsA = nullptr, *hsB = nullptr;
    float* biasp = nullptr;
    cudaGetSymbolAddress((void**)&hsA, g_hsA);
    cudaGetSymbolAddress((void**)&hsB, g_hsB);
    cudaGetSymbolAddress((void**)&biasp, g_bias);

    prep_kernel<<<LL * G4 / 256, 256>>>(b_ih, b_hh);

    // Layer 0 (fused, padded K=16 input chunk)
    lstm_rec_f16<true><<<BB / 8, 256>>>(
        x, nullptr, W_ih0, W_hh, biasp, hsA, 1);

    // Layers 1-3 (fused)
    __half* hs_in  = hsA;
    __half* hs_out = hsB;
    for (int l = 1; l < LL; ++l) {
        lstm_rec_f16<false><<<BB / 8, 256>>>(
            nullptr, hs_in,
            W_ihr + (size_t)(l - 1) * (G4 * HH),
            W_hh + (size_t)l * (G4 * HH),
            biasp + l * G4,
            hs_out, l < LL - 1 ? 1 : 0);
        __half* tmp = hs_in; hs_in = hs_out; hs_out = tmp;
    }

    fc_kernel<<<(BB * OUTN + 255) / 256, 256>>>(hs_in, W_fc, b_fc, out);
}

// round 17
// speedup vs baseline: 1.0091x; 1.0091x over previous
#include <cuda_runtime.h>
#include <cuda_fp16.h>
#include <cstddef>
#include <cstdint>

// Problem constants
#define BB   2048
#define TT   512
#define D_IN 4
#define HH   64
#define LL   4
#define OUTN 5
#define G4   256   // 4*H

// -------------------------- device scratch --------------------------------
__device__ __half g_hsA[(size_t)TT * BB * HH];    // 128 MB ping (half)
__device__ __half g_hsB[(size_t)TT * BB * HH];    // 128 MB pong (half)
__device__ float  g_bias[LL][G4];

__device__ __forceinline__ float tanhf_fast(float x) {
    float r;
    asm("tanh.approx.f32 %0, %1;" : "=f"(r) : "f"(x));
    return r;
}
__device__ __forceinline__ float sigf_fast(float x) {
    return fmaf(tanhf_fast(0.5f * x), 0.5f, 0.5f);
}

union H2U { __half2 h; uint32_t u; };
__device__ __forceinline__ uint32_t pack_h2(float a, float b) {
    H2U v; v.h = __floats2half2_rn(a, b); return v.u;
}

// fp16 MMA, f32 accumulate: A row-major 16x16, B col-major 16x8.
#define MMA_F16(c, a0, a1, a2, a3, b) \
    asm volatile("mma.sync.aligned.m16n8k16.row.col.f32.f16.f16.f32 " \
        "{%0,%1,%2,%3}, {%4,%5,%6,%7}, {%8,%9}, {%0,%1,%2,%3};" \
        : "+f"((c)[0]), "+f"((c)[1]), "+f"((c)[2]), "+f"((c)[3]) \
        : "r"(a0), "r"(a1), "r"(a2), "r"(a3), \
          "r"((b)[0]), "r"((b)[1]))

// h tile: 16 rows x 64 halfs, row stride 72 halfs (36 words).
#define ASTRH 72

// ---------------------------------------------------------------------------
__global__ void prep_kernel(const float* __restrict__ b_ih,
                            const float* __restrict__ b_hh) {
    int idx = blockIdx.x * blockDim.x + threadIdx.x;
    if (idx >= LL * G4) return;
    g_bias[idx >> 8][idx & 255] = b_ih[idx] + b_hh[idx];
}

// ====================== fused fp16 recurrence (all layers) =================
// R14 base (16 rows/CTA, 256 thr, 1 CTA/SM) with:
//   - MUFU.TANH epilogue (sig via tanh identity)
//   - x fragments in registers (GMEM prefetch, no Ax SMEM): x-MMAs for t+1
//     issued between h-MMAs and epilogue of t (fills the MUFU window).
template <bool L0>
__global__ void __launch_bounds__(256, 1)
lstm_rec_f16(const float* __restrict__ xin, const __half* __restrict__ hs_prev,
             const float* __restrict__ Wih, const float* __restrict__ Whh,
             const float* __restrict__ bias, __half* __restrict__ ouths,
             int write_all) {
    __shared__ __half Ah[2][16 * ASTRH];

    const int tid  = threadIdx.x;
    const int wid  = tid >> 5;
    const int lane = tid & 31;
    const int lr   = lane >> 2;
    const int lc   = lane & 3;
    const int rowbase = blockIdx.x * 16;
    constexpr int XKC = L0 ? 1 : 4;

    // ---- weight fragments -> registers ----
    uint32_t bfh[4][4][2];
    uint32_t bfi[4][XKC][2];
    {
        int n = wid * 8 + lr;
        #pragma unroll
        for (int q = 0; q < 4; ++q) {
            int g = q * 64 + n;
            #pragma unroll
            for (int kc = 0; kc < 4; ++kc) {
                int kb = kc * 16;
                bfh[q][kc][0] = pack_h2(Whh[g * HH + kb + 2 * lc],
                                        Whh[g * HH + kb + 2 * lc + 1]);
                bfh[q][kc][1] = pack_h2(Whh[g * HH + kb + 2 * lc + 8],
                                        Whh[g * HH + kb + 2 * lc + 9]);
            }
            if (L0) {
                uint32_t b0 = 0;
                if (lc < 2)
                    b0 = pack_h2(Wih[g * D_IN + 2 * lc],
                                 Wih[g * D_IN + 2 * lc + 1]);
                bfi[q][0][0] = b0;
                bfi[q][0][1] = 0;
            } else {
                #pragma unroll
                for (int kc = 0; kc < 4; ++kc) {
                    int kb = kc * 16;
                    bfi[q][kc][0] = pack_h2(Wih[g * HH + kb + 2 * lc],
                                            Wih[g * HH + kb + 2 * lc + 1]);
                    bfi[q][kc][1] = pack_h2(Wih[g * HH + kb + 2 * lc + 8],
                                            Wih[g * HH + kb + 2 * lc + 9]);
                }
            }
        }
    }

    const int u0 = wid * 8 + 2 * lc;
    float2 bias_r[4];
    #pragma unroll
    for (int q = 0; q < 4; ++q)
        bias_r[q] = *(const float2*)&bias[q * 64 + u0];

    // ---- init h = 0 ----
    for (int i = tid; i < 16 * ASTRH; i += 256) {
        Ah[0][i] = __float2half(0.f);
        Ah[1][i] = __float2half(0.f);
    }
    __syncthreads();

    // ---- x fragment loader (registers, MMA A layout; rows lr, lr+8) ----
    // xf[kc] = {a0,a1,a2,a3} for k-chunk kc.
    uint32_t xf[XKC][4];
    auto load_xfrag = [&](int t, uint32_t dst[XKC][4]) {
        if (L0) {
            uint32_t v0 = 0, v1 = 0;
            if (lc < 2) {
                float2 p0 = *(const float2*)
                    &xin[((size_t)(rowbase + lr) * TT + t) * D_IN + 2 * lc];
                float2 p1 = *(const float2*)
                    &xin[((size_t)(rowbase + lr + 8) * TT + t) * D_IN + 2 * lc];
                v0 = pack_h2(p0.x, p0.y);
                v1 = pack_h2(p1.x, p1.y);
            }
            dst[0][0] = v0; dst[0][1] = v1; dst[0][2] = 0; dst[0][3] = 0;
        } else {
            #pragma unroll
            for (int kc = 0; kc < XKC; ++kc) {
                const uint32_t* s0 = (const uint32_t*)
                    &hs_prev[((size_t)t * BB + rowbase + lr) * HH +
                             kc * 16 + 2 * lc];
                const uint32_t* s1 = (const uint32_t*)
                    &hs_prev[((size_t)t * BB + rowbase + lr + 8) * HH +
                             kc * 16 + 2 * lc];
                dst[kc][0] = s0[0];
                dst[kc][1] = s1[0];
                dst[kc][2] = s0[4];   // +8 halfs
                dst[kc][3] = s1[4];
            }
        }
    };

    // ---- prologue: accx = bias + x(0).Wih; xf <- x(1) ----
    float accx[4][4];
    load_xfrag(0, xf);
    #pragma unroll
    for (int q = 0; q < 4; ++q) {
        accx[q][0] = bias_r[q].x; accx[q][1] = bias_r[q].y;
        accx[q][2] = bias_r[q].x; accx[q][3] = bias_r[q].y;
    }
    #pragma unroll
    for (int kc = 0; kc < XKC; ++kc) {
        MMA_F16(accx[0], xf[kc][0], xf[kc][1], xf[kc][2], xf[kc][3], bfi[0][kc]);
        MMA_F16(accx[1], xf[kc][0], xf[kc][1], xf[kc][2], xf[kc][3], bfi[1][kc]);
        MMA_F16(accx[2], xf[kc][0], xf[kc][1], xf[kc][2], xf[kc][3], bfi[2][kc]);
        MMA_F16(accx[3], xf[kc][0], xf[kc][1], xf[kc][2], xf[kc][3], bfi[3][kc]);
    }
    load_xfrag(1, xf);   // x(1) for next accx

    float cst[4] = {0.f, 0.f, 0.f, 0.f};
    uint32_t* outu = (uint32_t*)ouths;

    for (int t = 0; t < TT; ++t) {
        const __half* Ahr = Ah[t & 1];
        __half*       Ahw = Ah[(t + 1) & 1];

        // ---- prefetch x(t+2) fragments (LDG, hidden under this step) ----
        uint32_t xn[XKC][4];
        if (t + 2 < TT) load_xfrag(t + 2, xn);

        // ---- acc = accx (bias + x(t) part), then h-MMAs ----
        float acc[4][4];
        #pragma unroll
        for (int q = 0; q < 4; ++q)
            #pragma unroll
            for (int j = 0; j < 4; ++j) acc[q][j] = accx[q][j];

        #pragma unroll
        for (int kc = 0; kc < 4; ++kc) {
            int k = kc * 16 + 2 * lc;
            uint32_t a0 = *(const uint32_t*)&Ahr[lr * ASTRH + k];
            uint32_t a1 = *(const uint32_t*)&Ahr[(lr + 8) * ASTRH + k];
            uint32_t a2 = *(const uint32_t*)&Ahr[lr * ASTRH + k + 8];
            uint32_t a3 = *(const uint32_t*)&Ahr[(lr + 8) * ASTRH + k + 8];
            MMA_F16(acc[0], a0, a1, a2, a3, bfh[0][kc]);
            MMA_F16(acc[1], a0, a1, a2, a3, bfh[1][kc]);
            MMA_F16(acc[2], a0, a1, a2, a3, bfh[2][kc]);
            MMA_F16(acc[3], a0, a1, a2, a3, bfh[3][kc]);
        }

        // ---- x-MMAs for t+1 (independent of epilogue; fills MUFU window) ----
        if (t + 1 < TT) {
            #pragma unroll
            for (int q = 0; q < 4; ++q) {
                accx[q][0] = bias_r[q].x; accx[q][1] = bias_r[q].y;
                accx[q][2] = bias_r[q].x; accx[q][3] = bias_r[q].y;
            }
            #pragma unroll
            for (int kc = 0; kc < XKC; ++kc) {
                MMA_F16(accx[0], xf[kc][0], xf[kc][1], xf[kc][2], xf[kc][3],
                        bfi[0][kc]);
                MMA_F16(accx[1], xf[kc][0], xf[kc][1], xf[kc][2], xf[kc][3],
                        bfi[1][kc]);
                MMA_F16(accx[2], xf[kc][0], xf[kc][1], xf[kc][2], xf[kc][3],
                        bfi[2][kc]);
                MMA_F16(accx[3], xf[kc][0], xf[kc][1], xf[kc][2], xf[kc][3],
                        bfi[3][kc]);
            }
        }

        // ---- epilogue: 2 rows x 2 units (MUFU.TANH fast path) ----
        #pragma unroll
        for (int rr = 0; rr < 2; ++rr) {
            int row = lr + 8 * rr;
            int j0  = rr * 2;
            float gi0 = sigf_fast(acc[0][j0]);
            float gf0 = sigf_fast(acc[1][j0]);
            float gg0 = tanhf_fast(acc[2][j0]);
            float go0 = sigf_fast(acc[3][j0]);
            float gi1 = sigf_fast(acc[0][j0 + 1]);
            float gf1 = sigf_fast(acc[1][j0 + 1]);
            float gg1 = tanhf_fast(acc[2][j0 + 1]);
            float go1 = sigf_fast(acc[3][j0 + 1]);

            float cn0 = gf0 * cst[j0]     + gi0 * gg0;
            float cn1 = gf1 * cst[j0 + 1] + gi1 * gg1;
            cst[j0]     = cn0;
            cst[j0 + 1] = cn1;
            float hn0 = go0 * tanhf_fast(cn0);
            float hn1 = go1 * tanhf_fast(cn1);

            uint32_t hpk = pack_h2(hn0, hn1);
            *(uint32_t*)&Ahw[row * ASTRH + u0] = hpk;

            if (write_all || t == TT - 1) {
                size_t trow = (size_t)t * BB + rowbase + row;
                outu[trow * 32 + 4 * wid + lc] = hpk;
            }
        }

        // ---- rotate x prefetch ----
        if (t + 2 < TT) {
            #pragma unroll
            for (int kc = 0; kc < XKC; ++kc) {
                xf[kc][0] = xn[kc][0]; xf[kc][1] = xn[kc][1];
                xf[kc][2] = xn[kc][2]; xf[kc][3] = xn[kc][3];
            }
        }
        __syncthreads();   // h(t+1) visible for next step
    }
}

// ---------------------------------------------------------------------------
__global__ void fc_kernel(const __half* __restrict__ hs,
                          const float* __restrict__ Wfc,
                          const float* __restrict__ bfc,
                          float* __restrict__ out) {
    int idx = blockIdx.x * blockDim.x + threadIdx.x;
    if (idx >= BB * OUTN) return;
    int b = idx / OUTN, o = idx - b * OUTN;
    const __half* h = &hs[(size_t)(TT - 1) * (BB * HH) + (size_t)b * HH];
    float s = bfc[o];
    #pragma unroll
    for (int j = 0; j < HH; j++)
        s = fmaf(__half2float(h[j]), Wfc[o * HH + j], s);
    out[idx] = s;
}

// ---------------------------------------------------------------------------
extern "C" void kernel_launch(void* const* d_in, const int* in_sizes, int n_in,
                              void* d_out, int out_size) {
    const float* x     = (const float*)d_in[0];
    const float* W_ih0 = (const float*)d_in[1];
    const float* W_ihr = (const float*)d_in[2];
    const float* W_hh  = (const float*)d_in[3];
    const float* b_ih  = (const float*)d_in[4];
    const float* b_hh  = (const float*)d_in[5];
    const float* W_fc  = (const float*)d_in[6];
    const float* b_fc  = (const float*)d_in[7];
    float* out = (float*)d_out;

    __half *hsA = nullptr, *hsB = nullptr;
    float* biasp = nullptr;
    cudaGetSymbolAddress((void**)&hsA, g_hsA);
    cudaGetSymbolAddress((void**)&hsB, g_hsB);
    cudaGetSymbolAddress((void**)&biasp, g_bias);

    prep_kernel<<<LL * G4 / 256, 256>>>(b_ih, b_hh);

    // Layer 0 (fused, padded K=16 input chunk)
    lstm_rec_f16<true><<<BB / 16, 256>>>(
        x, nullptr, W_ih0, W_hh, biasp, hsA, 1);

    // Layers 1-3 (fused)
    __half* hs_in  = hsA;
    __half* hs_out = hsB;
    for (int l = 1; l < LL; ++l) {
        lstm_rec_f16<false><<<BB / 16, 256>>>(
            nullptr, hs_in,
            W_ihr + (size_t)(l - 1) * (G4 * HH),
            W_hh + (size_t)l * (G4 * HH),
            biasp + l * G4,
            hs_out, l < LL - 1 ? 1 : 0);
        __half* tmp = hs_in; hs_in = hs_out; hs_out = tmp;
    }

    fc_kernel<<<(BB * OUTN + 255) / 256, 256>>>(hs_in, W_fc, b_fc, out);
}